// round 4
// baseline (speedup 1.0000x reference)
#include <cuda_runtime.h>

#define NP 9216      // H*W
#define C  256
#define CO 32        // C/8

// ---------------- device scratch (no dynamic allocation) -------------------
__device__ float g_Y[CO * NP];    // Y[o][i], i = w*96+h
__device__ float g_n2[NP];        // ||y_i||^2
__device__ float g_Z[NP];         // row sums of exp(A - s_i)
__device__ float g_sv[NP];        // per-row shift s_i
__device__ float g_V[NP * C];     // V[i][c] = x5[c,i]/Z_i
__device__ float g_P[C * NP];     // P[c][j]
__device__ float g_cmax[C];
__device__ float g_cisum[C];
__device__ int   g_Mbits;

// ---------------- packed f32x2 helpers -------------------------------------
__device__ __forceinline__ unsigned long long pack2(float s) {
    unsigned long long r;
    asm("mov.b64 %0,{%1,%1};" : "=l"(r) : "r"(__float_as_uint(s)));
    return r;
}
__device__ __forceinline__ void fma2(unsigned long long& d,
                                     unsigned long long a, unsigned long long b) {
    asm("fma.rn.f32x2 %0,%1,%2,%0;" : "+l"(d) : "l"(a), "l"(b));
}
__device__ __forceinline__ void unpack2(unsigned long long v, float& lo, float& hi) {
    asm("mov.b64 {%0,%1},%2;" : "=f"(lo), "=f"(hi) : "l"(v));
}

// ---------------- k0: reset global max (every graph replay) ----------------
__global__ void k0_init() { if (threadIdx.x == 0) g_Mbits = 0; }

// ---------------- k1: 1x1 conv -> Y (i = w*96+h), n2, M --------------------
__global__ void __launch_bounds__(128) k1_conv(const float* __restrict__ x,
                                               const float* __restrict__ wc,
                                               const float* __restrict__ bc) {
    __shared__ float ws[C * CO];
    __shared__ float bs[CO];
    int t = threadIdx.x;
    for (int idx = t; idx < C * CO; idx += 128)
        ws[idx] = wc[(idx & 31) * C + (idx >> 5)];   // ws[c*32+o]
    if (t < CO) bs[t] = bc[t];
    __syncthreads();

    int pos = blockIdx.x * 128 + t;                  // h*96 + w
    float acc[CO];
#pragma unroll
    for (int o = 0; o < CO; o++) acc[o] = bs[o];
#pragma unroll 4
    for (int c = 0; c < C; c++) {
        float xv = x[c * NP + pos];
        const float4* wp = (const float4*)&ws[c * CO];
#pragma unroll
        for (int q = 0; q < 8; q++) {
            float4 w4 = wp[q];
            acc[q * 4 + 0] += w4.x * xv;
            acc[q * 4 + 1] += w4.y * xv;
            acc[q * 4 + 2] += w4.z * xv;
            acc[q * 4 + 3] += w4.w * xv;
        }
    }
    int h = pos / 96, w = pos - h * 96;
    int i = w * 96 + h;                              // transposed spatial index
    float ss = 0.0f;
#pragma unroll
    for (int o = 0; o < CO; o++) {
        g_Y[o * NP + i] = acc[o];
        ss += acc[o] * acc[o];
    }
    g_n2[i] = ss;
    atomicMax(&g_Mbits, __float_as_int(ss));         // ss>=0: bit-compare exact
}

// ---------------- k2: Z_i = sum_j exp(y_i.y_j - s_i) -----------------------
// grid 288 (i-tiles of 32), 256 thr: warp cg owns i = cg*4..cg*4+3, lanes = j
__global__ void __launch_bounds__(256) k2_zsum() {
    __shared__ float Yis[CO][32];
    __shared__ float Yjs[CO][32];
    int t = threadIdx.x, lane = t & 31, cg = t >> 5;
    int i0 = blockIdx.x * 32, ib = cg * 4;

    for (int o = cg; o < CO; o += 8) Yis[o][lane] = g_Y[o * NP + i0 + lane];

    float M = __int_as_float(g_Mbits);
    float sh[4], z[4] = {0.f, 0.f, 0.f, 0.f};
#pragma unroll
    for (int a = 0; a < 4; a++) sh[a] = sqrtf(g_n2[i0 + ib + a] * M);

    for (int j0 = 0; j0 < NP; j0 += 32) {
        __syncthreads();
        for (int o = cg; o < CO; o += 8) Yjs[o][lane] = g_Y[o * NP + j0 + lane];
        __syncthreads();
        float s[4] = {0.f, 0.f, 0.f, 0.f};
#pragma unroll
        for (int o = 0; o < CO; o++) {
            float4 q4 = *(const float4*)&Yis[o][ib];
            float kv = Yjs[o][lane];
            s[0] += q4.x * kv; s[1] += q4.y * kv;
            s[2] += q4.z * kv; s[3] += q4.w * kv;
        }
#pragma unroll
        for (int a = 0; a < 4; a++) z[a] += __expf(s[a] - sh[a]);
    }
#pragma unroll
    for (int a = 0; a < 4; a++) {
        float v = z[a];
        for (int off = 16; off; off >>= 1) v += __shfl_xor_sync(~0u, v, off);
        if (lane == 0) { g_Z[i0 + ib + a] = v; g_sv[i0 + ib + a] = sh[a]; }
    }
}

// ---------------- k2v: V[i][c] = x[c][i] / Z_i  (tiled transpose) ----------
__global__ void __launch_bounds__(256) k2v_buildV(const float* __restrict__ x) {
    __shared__ float T[32][33];
    int t = threadIdx.x, lane = t & 31, r = t >> 5;
    int i0 = blockIdx.x * 32, c0 = blockIdx.y * 32;
    for (int cc = r; cc < 32; cc += 8)
        T[cc][lane] = x[(c0 + cc) * NP + i0 + lane];
    __syncthreads();
    for (int rr = r; rr < 32; rr += 8) {
        float inv = __fdividef(1.0f, g_Z[i0 + rr]);
        g_V[(i0 + rr) * C + c0 + lane] = T[lane][rr] * inv;
    }
}

// ---------------- k3: P[c][j] = sum_i V[i][c] * exp(y_i.y_j - s_i) ---------
// grid 288 (j-tiles of 32), 256 thr: lane = j, cg = c-group (32 channels)
__global__ void __launch_bounds__(256) k3_pv() {
    __shared__ float Yjs[CO][32];
    __shared__ float Yis[CO][32];
    __shared__ float ws[32][32];
    __shared__ float Vs[32][C];
    int t = threadIdx.x, lane = t & 31, cg = t >> 5;
    int j0 = blockIdx.x * 32, ib = cg * 4, cb = cg * 32;

    for (int o = cg; o < CO; o += 8) Yjs[o][lane] = g_Y[o * NP + j0 + lane];

    unsigned long long acc[16];
#pragma unroll
    for (int k = 0; k < 16; k++) acc[k] = 0ull;      // {0.f, 0.f}

    for (int i0 = 0; i0 < NP; i0 += 32) {
        __syncthreads();
        for (int o = cg; o < CO; o += 8) Yis[o][lane] = g_Y[o * NP + i0 + lane];
#pragma unroll
        for (int q = 0; q < 8; q++) {                // stage V tile (32x256)
            int idx = t + q * 256;
            int row = idx >> 6, cq = idx & 63;
            *(float4*)&Vs[row][cq * 4] =
                *(const float4*)&g_V[(i0 + row) * C + cq * 4];
        }
        __syncthreads();
        // S phase: S[i][j] for this i-chunk, then w = exp(S - s_i)
        float s[4] = {0.f, 0.f, 0.f, 0.f};
#pragma unroll
        for (int o = 0; o < CO; o++) {
            float4 q4 = *(const float4*)&Yis[o][ib];
            float kv = Yjs[o][lane];
            s[0] += q4.x * kv; s[1] += q4.y * kv;
            s[2] += q4.z * kv; s[3] += q4.w * kv;
        }
#pragma unroll
        for (int a = 0; a < 4; a++)
            ws[ib + a][lane] = __expf(s[a] - g_sv[i0 + ib + a]);
        __syncthreads();
        // accumulate P[j][cb..cb+31] += w[i][j] * V[i][c]  (packed f32x2)
        for (int ii = 0; ii < 32; ii++) {
            unsigned long long wv = pack2(ws[ii][lane]);
            const ulonglong2* vp = (const ulonglong2*)&Vs[ii][cb];
#pragma unroll
            for (int k = 0; k < 8; k++) {
                ulonglong2 v = vp[k];
                fma2(acc[2 * k + 0], v.x, wv);
                fma2(acc[2 * k + 1], v.y, wv);
            }
        }
    }
#pragma unroll
    for (int k = 0; k < 16; k++) {
        float lo, hi;
        unpack2(acc[k], lo, hi);
        g_P[(cb + 2 * k + 0) * NP + j0 + lane] = lo;
        g_P[(cb + 2 * k + 1) * NP + j0 + lane] = hi;
    }
}

// ---------------- k4: per-channel softmax stats over j ---------------------
__global__ void __launch_bounds__(256) k4_cstats() {
    __shared__ float red[8];
    int c = blockIdx.x, t = threadIdx.x, lane = t & 31, w = t >> 5;
    const float* p = &g_P[c * NP];
    float m = -1e30f;
    for (int j = t; j < NP; j += 256) m = fmaxf(m, p[j]);
    for (int off = 16; off; off >>= 1) m = fmaxf(m, __shfl_xor_sync(~0u, m, off));
    if (lane == 0) red[w] = m;
    __syncthreads();
    m = red[0];
#pragma unroll
    for (int k = 1; k < 8; k++) m = fmaxf(m, red[k]);
    float s = 0.f;
    for (int j = t; j < NP; j += 256) s += __expf(p[j] - m);
    for (int off = 16; off; off >>= 1) s += __shfl_xor_sync(~0u, s, off);
    __syncthreads();
    if (lane == 0) red[w] = s;
    __syncthreads();
    s = 0.f;
#pragma unroll
    for (int k = 0; k < 8; k++) s += red[k];
    if (t == 0) { g_cmax[c] = m; g_cisum[c] = 1.0f / s; }
}

// ---------------- k5: out = softmax_w( x6 + x ) ----------------------------
__global__ void __launch_bounds__(96) k5_out(const float* __restrict__ x,
                                             float* __restrict__ out) {
    __shared__ float red[3];
    int b = blockIdx.x;
    int c = b / 96, h = b - c * 96;
    int t = threadIdx.x, lane = t & 31, w = t >> 5;
    int base = c * NP + h * 96;
    float v = __expf(g_P[base + t] - g_cmax[c]) * g_cisum[c] + x[base + t];
    float m = v;
    for (int off = 16; off; off >>= 1) m = fmaxf(m, __shfl_xor_sync(~0u, m, off));
    if (lane == 0) red[w] = m;
    __syncthreads();
    m = fmaxf(red[0], fmaxf(red[1], red[2]));
    float e = __expf(v - m);
    float s = e;
    for (int off = 16; off; off >>= 1) s += __shfl_xor_sync(~0u, s, off);
    __syncthreads();
    if (lane == 0) red[w] = s;
    __syncthreads();
    s = red[0] + red[1] + red[2];
    out[base + t] = e / s;
}

// ---------------- launch ---------------------------------------------------
extern "C" void kernel_launch(void* const* d_in, const int* in_sizes, int n_in,
                              void* d_out, int out_size) {
    const float* x  = (const float*)d_in[0];
    const float* wc = (const float*)d_in[1];
    const float* bc = (const float*)d_in[2];
    float* out = (float*)d_out;

    k0_init<<<1, 32>>>();
    k1_conv<<<72, 128>>>(x, wc, bc);
    k2_zsum<<<288, 256>>>();
    k2v_buildV<<<dim3(288, 8), 256>>>(x);
    k3_pv<<<288, 256>>>();
    k4_cstats<<<256, 256>>>();
    k5_out<<<24576, 96>>>(x, out);
}

// round 6
// speedup vs baseline: 1.1609x; 1.1609x over previous
#include <cuda_runtime.h>

#define NP 9216      // H*W
#define C  256
#define CO 32        // C/8

typedef unsigned long long ull;

// ---------------- device scratch (no dynamic allocation) -------------------
__device__ float g_Y[CO * NP];     // Y[o][i], i = w*96+h
__device__ float g_n2[NP];         // ||y_i||^2
__device__ float g_invZ[NP];       // 1 / row-sum of exp(A - s_i)
__device__ float g_sv[NP];         // per-row shift s_i
__device__ float g_V[NP * C];      // V[i][c] = x[c*NP+i]   (unscaled transpose)
__device__ float g_P[C * NP];      // P[c][j]
__device__ float g_cmax[C];
__device__ float g_cisum[C];
__device__ int   g_Mbits;

// ---------------- packed f32x2 helpers -------------------------------------
__device__ __forceinline__ ull pack2(float s) {
    ull r; asm("mov.b64 %0,{%1,%1};" : "=l"(r) : "r"(__float_as_uint(s)));
    return r;
}
__device__ __forceinline__ ull packlh(float lo, float hi) {
    ull r; asm("mov.b64 %0,{%1,%2};" : "=l"(r)
               : "r"(__float_as_uint(lo)), "r"(__float_as_uint(hi)));
    return r;
}
__device__ __forceinline__ void fma2(ull& d, ull a, ull b) {
    asm("fma.rn.f32x2 %0,%1,%2,%0;" : "+l"(d) : "l"(a), "l"(b));
}
__device__ __forceinline__ void unpack2(ull v, float& lo, float& hi) {
    asm("mov.b64 {%0,%1},%2;" : "=f"(lo), "=f"(hi) : "l"(v));
}

// ---------------- k0: reset global max (every graph replay) ----------------
__global__ void k0_init() { if (threadIdx.x == 0) g_Mbits = 0; }

// ---------------- k1: 1x1 conv -> Y (i = w*96+h), n2, M --------------------
__global__ void __launch_bounds__(128) k1_conv(const float* __restrict__ x,
                                               const float* __restrict__ wc,
                                               const float* __restrict__ bc) {
    __shared__ float ws[C * CO];
    __shared__ float bs[CO];
    int t = threadIdx.x;
    for (int idx = t; idx < C * CO; idx += 128)
        ws[idx] = wc[(idx & 31) * C + (idx >> 5)];   // ws[c*32+o]
    if (t < CO) bs[t] = bc[t];
    __syncthreads();

    int pos = blockIdx.x * 128 + t;                  // h*96 + w
    float acc[CO];
#pragma unroll
    for (int o = 0; o < CO; o++) acc[o] = bs[o];
#pragma unroll 4
    for (int c = 0; c < C; c++) {
        float xv = x[c * NP + pos];
        const float4* wp = (const float4*)&ws[c * CO];
#pragma unroll
        for (int q = 0; q < 8; q++) {
            float4 w4 = wp[q];
            acc[q * 4 + 0] += w4.x * xv;
            acc[q * 4 + 1] += w4.y * xv;
            acc[q * 4 + 2] += w4.z * xv;
            acc[q * 4 + 3] += w4.w * xv;
        }
    }
    int h = pos / 96, w = pos - h * 96;
    int i = w * 96 + h;                              // transposed spatial index
    float ss = 0.0f;
#pragma unroll
    for (int o = 0; o < CO; o++) {
        g_Y[o * NP + i] = acc[o];
        ss += acc[o] * acc[o];
    }
    g_n2[i] = ss;
    atomicMax(&g_Mbits, __float_as_int(ss));         // ss>=0: bit-compare exact
}

// ---------------- k2v: V[i][c] = x[c][i]  (tiled transpose) ----------------
__global__ void __launch_bounds__(256) k2v_buildV(const float* __restrict__ x) {
    __shared__ float T[32][33];
    int t = threadIdx.x, lane = t & 31, r = t >> 5;
    int i0 = blockIdx.x * 32, c0 = blockIdx.y * 32;
    for (int cc = r; cc < 32; cc += 8)
        T[cc][lane] = x[(c0 + cc) * NP + i0 + lane];
    __syncthreads();
    for (int rr = r; rr < 32; rr += 8)
        g_V[(i0 + rr) * C + c0 + lane] = T[lane][rr];
}

// ---------------- k2: invZ_i, s_i  (packed i-pairs) ------------------------
// grid 144 (BI=64), 256 thr. Warp cg owns i = i0+cg*8 .. +7 as 4 f32x2 pairs.
__global__ void __launch_bounds__(256) k2_zsum() {
    __shared__ ull   Yis2[CO][32];   // [o][q]: q=cg*4+p -> {Y[o][ib+2p],Y[o][ib+2p+1]}
    __shared__ float Yjs[CO][32];
    int t = threadIdx.x, lane = t & 31, cg = t >> 5;
    int i0 = blockIdx.x * 64;
    int ibase = i0 + cg * 8;

    // pack Yis2 once
#pragma unroll
    for (int k = 0; k < 4; k++) {
        int e = t + k * 256;
        int o = e >> 5, q = e & 31;
        int ip = i0 + (q >> 2) * 8 + (q & 3) * 2;
        Yis2[o][q] = packlh(g_Y[o * NP + ip], g_Y[o * NP + ip + 1]);
    }

    float M = __int_as_float(g_Mbits);
    float sh[8], z[8];
#pragma unroll
    for (int m = 0; m < 8; m++) {
        sh[m] = sqrtf(g_n2[ibase + m] * M);
        z[m] = 0.0f;
    }

    for (int j0 = 0; j0 < NP; j0 += 32) {
        __syncthreads();
        for (int o = cg; o < CO; o += 8) Yjs[o][lane] = g_Y[o * NP + j0 + lane];
        __syncthreads();
        ull s2[4] = {0ull, 0ull, 0ull, 0ull};
#pragma unroll
        for (int o = 0; o < CO; o++) {
            ull kd = pack2(Yjs[o][lane]);
            const ulonglong2* qp = (const ulonglong2*)&Yis2[o][cg * 4];
            ulonglong2 qa = qp[0], qb = qp[1];
            fma2(s2[0], qa.x, kd);
            fma2(s2[1], qa.y, kd);
            fma2(s2[2], qb.x, kd);
            fma2(s2[3], qb.y, kd);
        }
#pragma unroll
        for (int p = 0; p < 4; p++) {
            float lo, hi;
            unpack2(s2[p], lo, hi);
            z[2 * p]     += __expf(lo - sh[2 * p]);
            z[2 * p + 1] += __expf(hi - sh[2 * p + 1]);
        }
    }
#pragma unroll
    for (int m = 0; m < 8; m++) {
        float v = z[m];
        for (int off = 16; off; off >>= 1) v += __shfl_xor_sync(~0u, v, off);
        if (lane == 0) {
            g_invZ[ibase + m] = 1.0f / v;
            g_sv[ibase + m] = sh[m];
        }
    }
}

// ---------------- k3: P[c][j] = sum_i V[i][c] * e^{y_i.y_j - s_i}/Z_i ------
// grid 144 (BJ=64, 1 block/SM), 256 thr. Thread: j-pair (lane, lane+32),
// channels cb..cb+31 (cb = warp*32). i-chunks of 32.
__global__ void __launch_bounds__(256) k3_pv() {
    __shared__ ull Yjs2[CO][32];          // {Y[o][j0+lane], Y[o][j0+32+lane]}
    __shared__ ull ws2[32][32];           // {w(i,j_lo), w(i,j_hi)}
    __shared__ __align__(16) float Vs[32][C];
    int t = threadIdx.x, lane = t & 31, cg = t >> 5;
    int j0 = blockIdx.x * 64, ib = cg * 4, cb = cg * 32;

#pragma unroll
    for (int r = 0; r < 4; r++) {
        int o = cg + 8 * r;
        Yjs2[o][lane] = packlh(g_Y[o * NP + j0 + lane],
                               g_Y[o * NP + j0 + 32 + lane]);
    }

    ull aL[16], aH[16];
#pragma unroll
    for (int k = 0; k < 16; k++) { aL[k] = 0ull; aH[k] = 0ull; }

    for (int ic = 0; ic < NP; ic += 32) {
        __syncthreads();
        // stage V tile (32 x 256 floats)
#pragma unroll
        for (int q = 0; q < 8; q++) {
            int idx = t + q * 256;
            int row = idx >> 6, c4 = idx & 63;
            ((float4*)Vs[row])[c4] = ((const float4*)&g_V[(ic + row) * C])[c4];
        }
        float sh_[4], iz_[4];
#pragma unroll
        for (int a = 0; a < 4; a++) {
            sh_[a] = g_sv[ic + ib + a];
            iz_[a] = g_invZ[ic + ib + a];
        }
        // S phase: packed over the thread's j-pair
        ull s2[4] = {0ull, 0ull, 0ull, 0ull};
#pragma unroll
        for (int o = 0; o < CO; o++) {
            float4 q4 = *(const float4*)&g_Y[o * NP + ic + ib];
            ull kp = Yjs2[o][lane];
            fma2(s2[0], pack2(q4.x), kp);
            fma2(s2[1], pack2(q4.y), kp);
            fma2(s2[2], pack2(q4.z), kp);
            fma2(s2[3], pack2(q4.w), kp);
        }
#pragma unroll
        for (int a = 0; a < 4; a++) {
            float lo, hi;
            unpack2(s2[a], lo, hi);
            float el = __expf(lo - sh_[a]) * iz_[a];
            float eh = __expf(hi - sh_[a]) * iz_[a];
            ws2[ib + a][lane] = packlh(el, eh);
        }
        __syncthreads();
        // PV: 32 fma2 per ii per thread
#pragma unroll 4
        for (int ii = 0; ii < 32; ii++) {
            float wl, wh;
            unpack2(ws2[ii][lane], wl, wh);
            ull wdl = pack2(wl), wdh = pack2(wh);
            const ulonglong2* vp = (const ulonglong2*)&Vs[ii][cb];
#pragma unroll
            for (int k = 0; k < 8; k++) {
                ulonglong2 v = vp[k];
                fma2(aL[2 * k],     v.x, wdl);
                fma2(aL[2 * k + 1], v.y, wdl);
                fma2(aH[2 * k],     v.x, wdh);
                fma2(aH[2 * k + 1], v.y, wdh);
            }
        }
    }
#pragma unroll
    for (int k = 0; k < 16; k++) {
        float lo, hi;
        unpack2(aL[k], lo, hi);
        g_P[(cb + 2 * k) * NP + j0 + lane]     = lo;
        g_P[(cb + 2 * k + 1) * NP + j0 + lane] = hi;
        unpack2(aH[k], lo, hi);
        g_P[(cb + 2 * k) * NP + j0 + 32 + lane]     = lo;
        g_P[(cb + 2 * k + 1) * NP + j0 + 32 + lane] = hi;
    }
}

// ---------------- k4: per-channel softmax stats over j ---------------------
__global__ void __launch_bounds__(256) k4_cstats() {
    __shared__ float red[8];
    int c = blockIdx.x, t = threadIdx.x, lane = t & 31, w = t >> 5;
    const float* p = &g_P[c * NP];
    float m = -1e30f;
    for (int j = t; j < NP; j += 256) m = fmaxf(m, p[j]);
    for (int off = 16; off; off >>= 1) m = fmaxf(m, __shfl_xor_sync(~0u, m, off));
    if (lane == 0) red[w] = m;
    __syncthreads();
    m = red[0];
#pragma unroll
    for (int k = 1; k < 8; k++) m = fmaxf(m, red[k]);
    float s = 0.f;
    for (int j = t; j < NP; j += 256) s += __expf(p[j] - m);
    for (int off = 16; off; off >>= 1) s += __shfl_xor_sync(~0u, s, off);
    __syncthreads();
    if (lane == 0) red[w] = s;
    __syncthreads();
    s = 0.f;
#pragma unroll
    for (int k = 0; k < 8; k++) s += red[k];
    if (t == 0) { g_cmax[c] = m; g_cisum[c] = 1.0f / s; }
}

// ---------------- k5: out = softmax_w( x6 + x ) ----------------------------
__global__ void __launch_bounds__(96) k5_out(const float* __restrict__ x,
                                             float* __restrict__ out) {
    __shared__ float red[3];
    int b = blockIdx.x;
    int c = b / 96, h = b - c * 96;
    int t = threadIdx.x, lane = t & 31, w = t >> 5;
    int base = c * NP + h * 96;
    float v = __expf(g_P[base + t] - g_cmax[c]) * g_cisum[c] + x[base + t];
    float m = v;
    for (int off = 16; off; off >>= 1) m = fmaxf(m, __shfl_xor_sync(~0u, m, off));
    if (lane == 0) red[w] = m;
    __syncthreads();
    m = fmaxf(red[0], fmaxf(red[1], red[2]));
    float e = __expf(v - m);
    float s = e;
    for (int off = 16; off; off >>= 1) s += __shfl_xor_sync(~0u, s, off);
    __syncthreads();
    if (lane == 0) red[w] = s;
    __syncthreads();
    s = red[0] + red[1] + red[2];
    out[base + t] = e / s;
}

// ---------------- launch ---------------------------------------------------
extern "C" void kernel_launch(void* const* d_in, const int* in_sizes, int n_in,
                              void* d_out, int out_size) {
    const float* x  = (const float*)d_in[0];
    const float* wc = (const float*)d_in[1];
    const float* bc = (const float*)d_in[2];
    float* out = (float*)d_out;

    k0_init<<<1, 32>>>();
    k1_conv<<<72, 128>>>(x, wc, bc);
    k2v_buildV<<<dim3(288, 8), 256>>>(x);
    k2_zsum<<<144, 256>>>();
    k3_pv<<<144, 256>>>();
    k4_cstats<<<256, 256>>>();
    k5_out<<<24576, 96>>>(x, out);
}

// round 7
// speedup vs baseline: 1.6330x; 1.4067x over previous
#include <cuda_runtime.h>

#define NP 9216      // H*W
#define C  256
#define CO 32        // C/8

typedef unsigned long long ull;

// ---------------- device scratch (no dynamic allocation) -------------------
__device__ float g_Y[CO * NP];     // Y[o][i], i = w*96+h
__device__ float g_n2[NP];         // ||y_i||^2
__device__ float g_Zp[4][NP];      // partial row sums (4 j-splits)
__device__ float g_invZ[NP];       // 1 / row-sum of exp(A - s_i)
__device__ float g_sv[NP];         // per-row shift s_i
__device__ float g_V[NP * C];      // V[i][c] = x[c*NP+i]   (unscaled transpose)
__device__ float g_P[C * NP];      // P[c][j], i-split 0
__device__ float g_Pb[C * NP];     // P[c][j], i-split 1
__device__ float g_cmax[C];
__device__ float g_cisum[C];
__device__ int   g_Mbits;

// ---------------- packed f32x2 helpers -------------------------------------
__device__ __forceinline__ ull pack2(float s) {
    ull r; asm("mov.b64 %0,{%1,%1};" : "=l"(r) : "r"(__float_as_uint(s)));
    return r;
}
__device__ __forceinline__ ull packlh(float lo, float hi) {
    ull r; asm("mov.b64 %0,{%1,%2};" : "=l"(r)
               : "r"(__float_as_uint(lo)), "r"(__float_as_uint(hi)));
    return r;
}
__device__ __forceinline__ void fma2(ull& d, ull a, ull b) {
    asm("fma.rn.f32x2 %0,%1,%2,%0;" : "+l"(d) : "l"(a), "l"(b));
}
__device__ __forceinline__ void unpack2(ull v, float& lo, float& hi) {
    asm("mov.b64 {%0,%1},%2;" : "=f"(lo), "=f"(hi) : "l"(v));
}

// ---------------- k0: reset global max (every graph replay) ----------------
__global__ void k0_init() { if (threadIdx.x == 0) g_Mbits = 0; }

// ---------------- k1: 1x1 conv -> Y (i = w*96+h), n2, M --------------------
__global__ void __launch_bounds__(128) k1_conv(const float* __restrict__ x,
                                               const float* __restrict__ wc,
                                               const float* __restrict__ bc) {
    __shared__ float ws[C * CO];
    __shared__ float bs[CO];
    int t = threadIdx.x;
    for (int idx = t; idx < C * CO; idx += 128)
        ws[idx] = wc[(idx & 31) * C + (idx >> 5)];   // ws[c*32+o]
    if (t < CO) bs[t] = bc[t];
    __syncthreads();

    int pos = blockIdx.x * 128 + t;                  // h*96 + w
    float acc[CO];
#pragma unroll
    for (int o = 0; o < CO; o++) acc[o] = bs[o];
#pragma unroll 4
    for (int c = 0; c < C; c++) {
        float xv = x[c * NP + pos];
        const float4* wp = (const float4*)&ws[c * CO];
#pragma unroll
        for (int q = 0; q < 8; q++) {
            float4 w4 = wp[q];
            acc[q * 4 + 0] += w4.x * xv;
            acc[q * 4 + 1] += w4.y * xv;
            acc[q * 4 + 2] += w4.z * xv;
            acc[q * 4 + 3] += w4.w * xv;
        }
    }
    int h = pos / 96, w = pos - h * 96;
    int i = w * 96 + h;                              // transposed spatial index
    float ss = 0.0f;
#pragma unroll
    for (int o = 0; o < CO; o++) {
        g_Y[o * NP + i] = acc[o];
        ss += acc[o] * acc[o];
    }
    g_n2[i] = ss;
    atomicMax(&g_Mbits, __float_as_int(ss));         // ss>=0: bit-compare exact
}

// ---------------- k2v: V[i][c] = x[c][i]  (tiled transpose) ----------------
__global__ void __launch_bounds__(256) k2v_buildV(const float* __restrict__ x) {
    __shared__ float T[32][33];
    int t = threadIdx.x, lane = t & 31, r = t >> 5;
    int i0 = blockIdx.x * 32, c0 = blockIdx.y * 32;
    for (int cc = r; cc < 32; cc += 8)
        T[cc][lane] = x[(c0 + cc) * NP + i0 + lane];
    __syncthreads();
    for (int rr = r; rr < 32; rr += 8)
        g_V[(i0 + rr) * C + c0 + lane] = T[lane][rr];
}

// ---------------- k2: partial Z over one j-quarter (packed i-pairs) --------
// grid (144, 4), 256 thr, 4 blocks/SM. Warp cg owns i = i0+cg*8 .. +7.
__global__ void __launch_bounds__(256, 4) k2_zsum() {
    __shared__ ull   Yis2[CO][32];   // [o][q]: q=cg*4+p -> {Y[o][ib+2p],Y[o][ib+2p+1]}
    __shared__ float Yjs[CO][32];
    int t = threadIdx.x, lane = t & 31, cg = t >> 5;
    int i0 = blockIdx.x * 64;
    int js = blockIdx.y;             // j-split 0..3
    int ibase = i0 + cg * 8;

    // pack Yis2 once
#pragma unroll
    for (int k = 0; k < 4; k++) {
        int e = t + k * 256;
        int o = e >> 5, q = e & 31;
        int ip = i0 + (q >> 2) * 8 + (q & 3) * 2;
        Yis2[o][q] = packlh(g_Y[o * NP + ip], g_Y[o * NP + ip + 1]);
    }

    float M = __int_as_float(g_Mbits);
    float sh[8], z[8];
#pragma unroll
    for (int m = 0; m < 8; m++) {
        sh[m] = sqrtf(g_n2[ibase + m] * M);
        z[m] = 0.0f;
    }

    int jlo = js * (NP / 4), jhi = jlo + NP / 4;
    for (int j0 = jlo; j0 < jhi; j0 += 32) {
        __syncthreads();
        for (int o = cg; o < CO; o += 8) Yjs[o][lane] = g_Y[o * NP + j0 + lane];
        __syncthreads();
        ull s2[4] = {0ull, 0ull, 0ull, 0ull};
#pragma unroll
        for (int o = 0; o < CO; o++) {
            ull kd = pack2(Yjs[o][lane]);
            const ulonglong2* qp = (const ulonglong2*)&Yis2[o][cg * 4];
            ulonglong2 qa = qp[0], qb = qp[1];
            fma2(s2[0], qa.x, kd);
            fma2(s2[1], qa.y, kd);
            fma2(s2[2], qb.x, kd);
            fma2(s2[3], qb.y, kd);
        }
#pragma unroll
        for (int p = 0; p < 4; p++) {
            float lo, hi;
            unpack2(s2[p], lo, hi);
            z[2 * p]     += __expf(lo - sh[2 * p]);
            z[2 * p + 1] += __expf(hi - sh[2 * p + 1]);
        }
    }
#pragma unroll
    for (int m = 0; m < 8; m++) {
        float v = z[m];
        for (int off = 16; off; off >>= 1) v += __shfl_xor_sync(~0u, v, off);
        if (lane == 0) g_Zp[js][ibase + m] = v;
    }
}

// ---------------- k2r: reduce Z partials -> invZ, sv -----------------------
__global__ void __launch_bounds__(256) k2r_reduce() {
    int i = blockIdx.x * 256 + threadIdx.x;
    float M = __int_as_float(g_Mbits);
    float z = ((g_Zp[0][i] + g_Zp[1][i]) + g_Zp[2][i]) + g_Zp[3][i];
    g_invZ[i] = 1.0f / z;
    g_sv[i] = sqrtf(g_n2[i] * M);
}

// ---------------- k3: P[c][j] = sum_i V[i][c] * e^{y_i.y_j - s_i}/Z_i ------
// grid (144, 2), 256 thr, 2 blocks/SM. blockIdx.y = i-half.
// Thread: j-pair (lane, lane+32), channels cb..cb+31. i-chunks of 32.
__global__ void __launch_bounds__(256, 2) k3_pv() {
    __shared__ ull Yjs2[CO][32];          // {Y[o][j0+lane], Y[o][j0+32+lane]}
    __shared__ ull ws2[32][32];           // {w(i,j_lo), w(i,j_hi)}
    __shared__ __align__(16) float Vs[32][C];
    int t = threadIdx.x, lane = t & 31, cg = t >> 5;
    int j0 = blockIdx.x * 64, ib = cg * 4, cb = cg * 32;
    int ihalf = blockIdx.y;
    int ilo = ihalf * (NP / 2), ihi = ilo + NP / 2;

#pragma unroll
    for (int r = 0; r < 4; r++) {
        int o = cg + 8 * r;
        Yjs2[o][lane] = packlh(g_Y[o * NP + j0 + lane],
                               g_Y[o * NP + j0 + 32 + lane]);
    }

    ull aL[16], aH[16];
#pragma unroll
    for (int k = 0; k < 16; k++) { aL[k] = 0ull; aH[k] = 0ull; }

    for (int ic = ilo; ic < ihi; ic += 32) {
        __syncthreads();
        // stage V tile (32 x 256 floats)
#pragma unroll
        for (int q = 0; q < 8; q++) {
            int idx = t + q * 256;
            int row = idx >> 6, c4 = idx & 63;
            ((float4*)Vs[row])[c4] = ((const float4*)&g_V[(ic + row) * C])[c4];
        }
        float sh_[4], iz_[4];
#pragma unroll
        for (int a = 0; a < 4; a++) {
            sh_[a] = g_sv[ic + ib + a];
            iz_[a] = g_invZ[ic + ib + a];
        }
        // S phase: packed over the thread's j-pair
        ull s2[4] = {0ull, 0ull, 0ull, 0ull};
#pragma unroll
        for (int o = 0; o < CO; o++) {
            float4 q4 = *(const float4*)&g_Y[o * NP + ic + ib];
            ull kp = Yjs2[o][lane];
            fma2(s2[0], pack2(q4.x), kp);
            fma2(s2[1], pack2(q4.y), kp);
            fma2(s2[2], pack2(q4.z), kp);
            fma2(s2[3], pack2(q4.w), kp);
        }
#pragma unroll
        for (int a = 0; a < 4; a++) {
            float lo, hi;
            unpack2(s2[a], lo, hi);
            float el = __expf(lo - sh_[a]) * iz_[a];
            float eh = __expf(hi - sh_[a]) * iz_[a];
            ws2[ib + a][lane] = packlh(el, eh);
        }
        __syncthreads();
        // PV: 32 fma2 per ii per thread
#pragma unroll 4
        for (int ii = 0; ii < 32; ii++) {
            float wl, wh;
            unpack2(ws2[ii][lane], wl, wh);
            ull wdl = pack2(wl), wdh = pack2(wh);
            const ulonglong2* vp = (const ulonglong2*)&Vs[ii][cb];
#pragma unroll
            for (int k = 0; k < 8; k++) {
                ulonglong2 v = vp[k];
                fma2(aL[2 * k],     v.x, wdl);
                fma2(aL[2 * k + 1], v.y, wdl);
                fma2(aH[2 * k],     v.x, wdh);
                fma2(aH[2 * k + 1], v.y, wdh);
            }
        }
    }
    float* Pout = ihalf ? g_Pb : g_P;
#pragma unroll
    for (int k = 0; k < 16; k++) {
        float lo, hi;
        unpack2(aL[k], lo, hi);
        Pout[(cb + 2 * k) * NP + j0 + lane]     = lo;
        Pout[(cb + 2 * k + 1) * NP + j0 + lane] = hi;
        unpack2(aH[k], lo, hi);
        Pout[(cb + 2 * k) * NP + j0 + 32 + lane]     = lo;
        Pout[(cb + 2 * k + 1) * NP + j0 + 32 + lane] = hi;
    }
}

// ---------------- k4: per-channel softmax stats over j ---------------------
__global__ void __launch_bounds__(256) k4_cstats() {
    __shared__ float red[8];
    int c = blockIdx.x, t = threadIdx.x, lane = t & 31, w = t >> 5;
    const float* p0 = &g_P[c * NP];
    const float* p1 = &g_Pb[c * NP];
    float m = -1e30f;
    for (int j = t; j < NP; j += 256) m = fmaxf(m, p0[j] + p1[j]);
    for (int off = 16; off; off >>= 1) m = fmaxf(m, __shfl_xor_sync(~0u, m, off));
    if (lane == 0) red[w] = m;
    __syncthreads();
    m = red[0];
#pragma unroll
    for (int k = 1; k < 8; k++) m = fmaxf(m, red[k]);
    float s = 0.f;
    for (int j = t; j < NP; j += 256) s += __expf(p0[j] + p1[j] - m);
    for (int off = 16; off; off >>= 1) s += __shfl_xor_sync(~0u, s, off);
    __syncthreads();
    if (lane == 0) red[w] = s;
    __syncthreads();
    s = 0.f;
#pragma unroll
    for (int k = 0; k < 8; k++) s += red[k];
    if (t == 0) { g_cmax[c] = m; g_cisum[c] = 1.0f / s; }
}

// ---------------- k5: out = softmax_w( x6 + x ) ----------------------------
__global__ void __launch_bounds__(96) k5_out(const float* __restrict__ x,
                                             float* __restrict__ out) {
    __shared__ float red[3];
    int b = blockIdx.x;
    int c = b / 96, h = b - c * 96;
    int t = threadIdx.x, lane = t & 31, w = t >> 5;
    int base = c * NP + h * 96;
    float pv = g_P[base + t] + g_Pb[base + t];
    float v = __expf(pv - g_cmax[c]) * g_cisum[c] + x[base + t];
    float m = v;
    for (int off = 16; off; off >>= 1) m = fmaxf(m, __shfl_xor_sync(~0u, m, off));
    if (lane == 0) red[w] = m;
    __syncthreads();
    m = fmaxf(red[0], fmaxf(red[1], red[2]));
    float e = __expf(v - m);
    float s = e;
    for (int off = 16; off; off >>= 1) s += __shfl_xor_sync(~0u, s, off);
    __syncthreads();
    if (lane == 0) red[w] = s;
    __syncthreads();
    s = red[0] + red[1] + red[2];
    out[base + t] = e / s;
}

// ---------------- launch ---------------------------------------------------
extern "C" void kernel_launch(void* const* d_in, const int* in_sizes, int n_in,
                              void* d_out, int out_size) {
    const float* x  = (const float*)d_in[0];
    const float* wc = (const float*)d_in[1];
    const float* bc = (const float*)d_in[2];
    float* out = (float*)d_out;

    k0_init<<<1, 32>>>();
    k1_conv<<<72, 128>>>(x, wc, bc);
    k2v_buildV<<<dim3(288, 8), 256>>>(x);
    k2_zsum<<<dim3(144, 4), 256>>>();
    k2r_reduce<<<36, 256>>>();
    k3_pv<<<dim3(144, 2), 256>>>();
    k4_cstats<<<256, 256>>>();
    k5_out<<<24576, 96>>>(x, out);
}